// round 1
// baseline (speedup 1.0000x reference)
#include <cuda_runtime.h>
#include <cstdint>

#define N_NODES 50000
#define N_EDGES 800000
#define NFEAT   128

// Scratch aggregation buffer (device global: no allocation allowed in kernel_launch).
__device__ float g_agg[(size_t)N_NODES * NFEAT];

// ---------------------------------------------------------------------------
// Kernel 1: zero the aggregation buffer (float4 stores, grid-stride).
// ---------------------------------------------------------------------------
__global__ void zero_agg_kernel() {
    size_t total4 = (size_t)N_NODES * NFEAT / 4;
    size_t i = (size_t)blockIdx.x * blockDim.x + threadIdx.x;
    float4* p = reinterpret_cast<float4*>(g_agg);
    for (; i < total4; i += (size_t)gridDim.x * blockDim.x) {
        p[i] = make_float4(0.f, 0.f, 0.f, 0.f);
    }
}

// ---------------------------------------------------------------------------
// Kernel 2: edge scatter — one warp per edge.
// lane l handles float4 at column l*4. Gather from feature[src], vector
// reduction (red.global.add.v4.f32, sm_90+) into g_agg[dst].
// ---------------------------------------------------------------------------
__global__ void edge_scatter_kernel(const float* __restrict__ feature,
                                    const int*   __restrict__ src_idx,
                                    const int*   __restrict__ dst_idx) {
    int warp = (int)((blockIdx.x * (size_t)blockDim.x + threadIdx.x) >> 5);
    int lane = threadIdx.x & 31;
    if (warp >= N_EDGES) return;

    int s = src_idx[warp];
    int d = dst_idx[warp];

    const float4 v = *reinterpret_cast<const float4*>(
        feature + (size_t)s * NFEAT + lane * 4);
    float* p = g_agg + (size_t)d * NFEAT + lane * 4;

    asm volatile("red.global.add.v4.f32 [%0], {%1, %2, %3, %4};"
                 :: "l"(p), "f"(v.x), "f"(v.y), "f"(v.z), "f"(v.w)
                 : "memory");
}

// ---------------------------------------------------------------------------
// Kernel 3: out = relu(agg @ W^T + b)
// agg: [N_NODES, 128]  W: [128(out), 128(in)] row-major  b: [128]
// Tiled SGEMM: BM=128, BN=128, BK=32, 256 threads, 8x8 register tile.
// ---------------------------------------------------------------------------
#define BM 128
#define BN 128
#define BK 32

__global__ __launch_bounds__(256, 2)
void gemm_bias_relu_kernel(const float* __restrict__ Wm,
                           const float* __restrict__ bias,
                           float* __restrict__ out) {
    __shared__ float As[BK][BM + 4];   // A transposed: [k][m]
    __shared__ float Ws[BK][BN + 4];   // W transposed: [k][n]

    const int tid = threadIdx.x;
    const int tm0 = (tid >> 4) << 3;   // 0..120, step 8 (16 groups)
    const int tn0 = (tid & 15) << 3;   // 0..120, step 8
    const int block_m = blockIdx.x * BM;

    float acc[8][8];
    #pragma unroll
    for (int i = 0; i < 8; i++)
        #pragma unroll
        for (int j = 0; j < 8; j++)
            acc[i][j] = 0.f;

    for (int k0 = 0; k0 < NFEAT; k0 += BK) {
        // Load A tile (128 rows x 32 k) transposed into As[k][m].
        // 4096 floats = 1024 float4; 4 float4 per thread.
        #pragma unroll
        for (int r = 0; r < 4; r++) {
            int idx = tid + r * 256;          // 0..1023
            int row = idx >> 3;               // 0..127
            int kq  = idx & 7;                // float4 index within BK
            int grow = block_m + row;
            float4 v = make_float4(0.f, 0.f, 0.f, 0.f);
            if (grow < N_NODES)
                v = *reinterpret_cast<const float4*>(
                    g_agg + (size_t)grow * NFEAT + k0 + kq * 4);
            As[kq * 4 + 0][row] = v.x;
            As[kq * 4 + 1][row] = v.y;
            As[kq * 4 + 2][row] = v.z;
            As[kq * 4 + 3][row] = v.w;
        }
        // Load W tile (128 n-rows x 32 k) transposed into Ws[k][n].
        #pragma unroll
        for (int r = 0; r < 4; r++) {
            int idx = tid + r * 256;
            int n  = idx >> 3;
            int kq = idx & 7;
            float4 v = *reinterpret_cast<const float4*>(
                Wm + (size_t)n * NFEAT + k0 + kq * 4);
            Ws[kq * 4 + 0][n] = v.x;
            Ws[kq * 4 + 1][n] = v.y;
            Ws[kq * 4 + 2][n] = v.z;
            Ws[kq * 4 + 3][n] = v.w;
        }
        __syncthreads();

        #pragma unroll
        for (int kk = 0; kk < BK; kk++) {
            float a[8], bvec[8];
            #pragma unroll
            for (int i = 0; i < 8; i++) a[i] = As[kk][tm0 + i];
            #pragma unroll
            for (int j = 0; j < 8; j++) bvec[j] = Ws[kk][tn0 + j];
            #pragma unroll
            for (int i = 0; i < 8; i++)
                #pragma unroll
                for (int j = 0; j < 8; j++)
                    acc[i][j] = fmaf(a[i], bvec[j], acc[i][j]);
        }
        __syncthreads();
    }

    // Epilogue: bias + relu, store.
    float bb[8];
    #pragma unroll
    for (int j = 0; j < 8; j++) bb[j] = bias[tn0 + j];

    #pragma unroll
    for (int i = 0; i < 8; i++) {
        int grow = block_m + tm0 + i;
        if (grow < N_NODES) {
            float4 o0, o1;
            o0.x = fmaxf(acc[i][0] + bb[0], 0.f);
            o0.y = fmaxf(acc[i][1] + bb[1], 0.f);
            o0.z = fmaxf(acc[i][2] + bb[2], 0.f);
            o0.w = fmaxf(acc[i][3] + bb[3], 0.f);
            o1.x = fmaxf(acc[i][4] + bb[4], 0.f);
            o1.y = fmaxf(acc[i][5] + bb[5], 0.f);
            o1.z = fmaxf(acc[i][6] + bb[6], 0.f);
            o1.w = fmaxf(acc[i][7] + bb[7], 0.f);
            float* op = out + (size_t)grow * NFEAT + tn0;
            *reinterpret_cast<float4*>(op)     = o0;
            *reinterpret_cast<float4*>(op + 4) = o1;
        }
    }
}

// ---------------------------------------------------------------------------
// kernel_launch
// Inputs (metadata order): feature [N,128] f32, src_idx [E] i32,
//                          dst_idx [E] i32, W [128,128] f32, b [128] f32
// Output: [N,128] f32
// ---------------------------------------------------------------------------
extern "C" void kernel_launch(void* const* d_in, const int* in_sizes, int n_in,
                              void* d_out, int out_size) {
    const float* feature = (const float*)d_in[0];
    const int*   src_idx = (const int*)d_in[1];
    const int*   dst_idx = (const int*)d_in[2];
    const float* Wm      = (const float*)d_in[3];
    const float* bias    = (const float*)d_in[4];
    float*       out     = (float*)d_out;

    // 1) zero aggregation scratch
    {
        int threads = 256;
        int blocks = 2048;
        zero_agg_kernel<<<blocks, threads>>>();
    }

    // 2) edge scatter: one warp per edge, 8 warps per block
    {
        int threads = 256;
        int warps_per_block = threads / 32;
        int blocks = (N_EDGES + warps_per_block - 1) / warps_per_block;
        edge_scatter_kernel<<<blocks, threads>>>(feature, src_idx, dst_idx);
    }

    // 3) GEMM + bias + relu
    {
        int blocks = (N_NODES + BM - 1) / BM;
        gemm_bias_relu_kernel<<<blocks, 256>>>(Wm, bias, out);
    }
}